// round 5
// baseline (speedup 1.0000x reference)
#include <cuda_runtime.h>

// ContrastiveLoss: z [8192,128] fp32, labels [8192] int32.
// loss = mean over all ordered pairs of: label_eq ? d2 : relu(1 - sqrt(max(d2,0)))^2
//
// pos: closed form per class: sum_{i,j in c} d2 = 2*n_c*S_c - 2*|M_c|^2  (O(N*D))
// neg: only pairs with d2 < 1 contribute. Partial squared distance over the first
//      PSCR dims is a LOWER bound on d2 -> screen at O(N^2*PSCR) with packed f32x2
//      FMA; exact 128-dim recheck for rare candidates (sound for any input).

#define NPTS   8192
#define DIM    128
#define NC     100
#define PSCR   8
#define TJ     256
#define NTHR   256
#define IPT    4
#define TI     (NTHR * IPT)       // 1024
#define THRESH 1.25f              // screen-out if partial d2 >= THRESH (1 + fp32 slack)

// ---- scratch (no allocations allowed) ----
__device__ double g_pos[NC];      // per-class analytic pos contribution (slot write, no atomics)
__device__ double g_neg;          // sum over unordered unequal pairs of relu(1-dist)^2
__device__ float  g_sq[NPTS];     // per-point squared norm

// ---------------- packed f32x2 helpers (Blackwell) --------------------------
__device__ __forceinline__ unsigned long long pack_dup(float x) {
    unsigned long long r;
    asm("mov.b64 %0, {%1, %1};" : "=l"(r) : "f"(x));
    return r;
}
__device__ __forceinline__ unsigned long long pack2(float lo, float hi) {
    unsigned long long r;
    asm("mov.b64 %0, {%1, %2};" : "=l"(r) : "f"(lo), "f"(hi));
    return r;
}
__device__ __forceinline__ void unpack2(unsigned long long v, float& lo, float& hi) {
    asm("mov.b64 {%0, %1}, %2;" : "=f"(lo), "=f"(hi) : "l"(v));
}
__device__ __forceinline__ unsigned long long fma2(unsigned long long a,
                                                   unsigned long long b,
                                                   unsigned long long c) {
    unsigned long long d;
    asm("fma.rn.f32x2 %0, %1, %2, %3;" : "=l"(d) : "l"(a), "l"(b), "l"(c));
    return d;
}
__device__ __forceinline__ unsigned long long add2(unsigned long long a,
                                                   unsigned long long b) {
    unsigned long long d;
    asm("add.rn.f32x2 %0, %1, %2;" : "=l"(d) : "l"(a), "l"(b));
    return d;
}

// ---------------- per-point squared norms (+ zero g_neg) --------------------
__global__ void k_sq(const float* __restrict__ z) {
    int i = blockIdx.x * blockDim.x + threadIdx.x;
    if (i == 0) g_neg = 0.0;
    if (i < NPTS) {
        const float4* zr = (const float4*)(z + (size_t)i * DIM);
        float s = 0.0f;
#pragma unroll
        for (int k = 0; k < DIM / 4; k++) {
            float4 v = zr[k];
            s = fmaf(v.x, v.x, s); s = fmaf(v.y, v.y, s);
            s = fmaf(v.z, v.z, s); s = fmaf(v.w, v.w, s);
        }
        g_sq[i] = s;
    }
}

// ---------------- per-class analytic pos term (block = class) ---------------
__global__ void __launch_bounds__(128)
k_class(const float* __restrict__ z, const int* __restrict__ lab) {
    __shared__ int    list[NPTS];      // member row indices (32KB)
    __shared__ int    s_cnt;
    __shared__ double red[128];
    const int c   = blockIdx.x;
    const int tid = threadIdx.x;

    if (tid == 0) s_cnt = 0;
    __syncthreads();
    for (int i = tid; i < NPTS; i += 128)
        if (lab[i] == c) list[atomicAdd(&s_cnt, 1)] = i;
    __syncthreads();
    const int cnt = s_cnt;

    // column pass: thread owns dim `tid`; warp lanes read consecutive dims of
    // the same row -> coalesced 128B lines, L2-resident.
    double acc = 0.0;
    {
        float m = 0.0f, ssq = 0.0f;
        for (int k = 0; k < cnt; k++) {
            float v = __ldg(z + (size_t)list[k] * DIM + tid);
            m += v;
            ssq = fmaf(v, v, ssq);
        }
        // contribution of this dim: 2*cnt*ssq_d - 2*m_d^2 ; summed over dims
        acc = 2.0 * (double)cnt * (double)ssq - 2.0 * (double)m * (double)m;
    }
    red[tid] = acc;
    __syncthreads();
    for (int s = 64; s > 0; s >>= 1) {
        if (tid < s) red[tid] += red[tid + s];
        __syncthreads();
    }
    if (tid == 0) g_pos[c] = red[0];
}

// ---------------- screening pass over unordered pairs (j > i) ---------------
__global__ void __launch_bounds__(NTHR)
k_screen(const float* __restrict__ z, const int* __restrict__ lab) {
    // j-tile staged PRE-DUPLICATED for packed FMA (no per-j pack movs)
    __shared__ ulonglong2          sZd[TJ][PSCR / 2];   // [j][k2]: (dup z_{2k2}, dup z_{2k2+1})
    __shared__ unsigned long long  sPd[TJ];             // dup(partial sq norm of j)

    const int I0 = blockIdx.y * TI;
    const int J0 = blockIdx.x * TJ;
    if (J0 < I0) return;                          // no pair with j > i in this block
    const bool needCheck = (J0 < I0 + TI);        // diagonal overlap -> per-pair j>i check

    const int tid = threadIdx.x;

    // stage j tile
    for (int j = tid; j < TJ; j += NTHR) {
        int jg = J0 + j;
        const float4* zr = (const float4*)(z + (size_t)jg * DIM);
        float4 v0 = zr[0], v1 = zr[1];
        float s = v0.x * v0.x + v0.y * v0.y + v0.z * v0.z + v0.w * v0.w
                + v1.x * v1.x + v1.y * v1.y + v1.z * v1.z + v1.w * v1.w;
        sZd[j][0] = make_ulonglong2(pack_dup(v0.x), pack_dup(v0.y));
        sZd[j][1] = make_ulonglong2(pack_dup(v0.z), pack_dup(v0.w));
        sZd[j][2] = make_ulonglong2(pack_dup(v1.x), pack_dup(v1.y));
        sZd[j][3] = make_ulonglong2(pack_dup(v1.z), pack_dup(v1.w));
        sPd[j] = pack_dup(s);
    }
    __syncthreads();

    // 4 i-rows per thread, packed as 2 pairs: rn[p][k] = (-2*z_ia[k], -2*z_ib[k])
    unsigned long long rn[2][PSCR];
    unsigned long long ps2[2];
#pragma unroll
    for (int p = 0; p < 2; p++) {
        int ia = I0 + tid + (2 * p) * NTHR;
        int ib = ia + NTHR;
        const float4* za = (const float4*)(z + (size_t)ia * DIM);
        const float4* zb = (const float4*)(z + (size_t)ib * DIM);
        float4 a0 = za[0], a1 = za[1], b0 = zb[0], b1 = zb[1];
        float sa = a0.x*a0.x + a0.y*a0.y + a0.z*a0.z + a0.w*a0.w
                 + a1.x*a1.x + a1.y*a1.y + a1.z*a1.z + a1.w*a1.w;
        float sb = b0.x*b0.x + b0.y*b0.y + b0.z*b0.z + b0.w*b0.w
                 + b1.x*b1.x + b1.y*b1.y + b1.z*b1.z + b1.w*b1.w;
        rn[p][0] = pack2(-2.0f * a0.x, -2.0f * b0.x);
        rn[p][1] = pack2(-2.0f * a0.y, -2.0f * b0.y);
        rn[p][2] = pack2(-2.0f * a0.z, -2.0f * b0.z);
        rn[p][3] = pack2(-2.0f * a0.w, -2.0f * b0.w);
        rn[p][4] = pack2(-2.0f * a1.x, -2.0f * b1.x);
        rn[p][5] = pack2(-2.0f * a1.y, -2.0f * b1.y);
        rn[p][6] = pack2(-2.0f * a1.z, -2.0f * b1.z);
        rn[p][7] = pack2(-2.0f * a1.w, -2.0f * b1.w);
        ps2[p] = pack2(sa, sb);
    }

    for (int j = 0; j < TJ; j++) {
        ulonglong2 z0 = sZd[j][0], z1 = sZd[j][1], z2 = sZd[j][2], z3 = sZd[j][3];
        unsigned long long pj = sPd[j];

        // packed partial d2: pd2 = psq_i + psq_j - 2*dot  (lower bound on full d2)
        unsigned long long a0 = add2(ps2[0], pj);
        a0 = fma2(rn[0][0], z0.x, a0); a0 = fma2(rn[0][1], z0.y, a0);
        a0 = fma2(rn[0][2], z1.x, a0); a0 = fma2(rn[0][3], z1.y, a0);
        a0 = fma2(rn[0][4], z2.x, a0); a0 = fma2(rn[0][5], z2.y, a0);
        a0 = fma2(rn[0][6], z3.x, a0); a0 = fma2(rn[0][7], z3.y, a0);

        unsigned long long a1 = add2(ps2[1], pj);
        a1 = fma2(rn[1][0], z0.x, a1); a1 = fma2(rn[1][1], z0.y, a1);
        a1 = fma2(rn[1][2], z1.x, a1); a1 = fma2(rn[1][3], z1.y, a1);
        a1 = fma2(rn[1][4], z2.x, a1); a1 = fma2(rn[1][5], z2.y, a1);
        a1 = fma2(rn[1][6], z3.x, a1); a1 = fma2(rn[1][7], z3.y, a1);

        float x0, x1, x2, x3;
        unpack2(a0, x0, x1);
        unpack2(a1, x2, x3);
        float mn = fminf(fminf(x0, x1), fminf(x2, x3));

        if (mn < THRESH) {                        // rare (~3e-4 of pairs)
            int jg = J0 + j;
            int lj = lab[jg];
            float sqj = g_sq[jg];
            const float4* zb = (const float4*)(z + (size_t)jg * DIM);
#pragma unroll
            for (int t = 0; t < IPT; t++) {
                int ig = I0 + tid + t * NTHR;
                if ((!needCheck || jg > ig) && lab[ig] != lj) {
                    // exact 128-dim recheck, same formula as the reference
                    const float4* za = (const float4*)(z + (size_t)ig * DIM);
                    float dot = 0.0f;
#pragma unroll
                    for (int k = 0; k < DIM / 4; k++) {
                        float4 a = za[k], b = zb[k];
                        dot = fmaf(a.x, b.x, dot); dot = fmaf(a.y, b.y, dot);
                        dot = fmaf(a.z, b.z, dot); dot = fmaf(a.w, b.w, dot);
                    }
                    float d2 = g_sq[ig] + sqj - 2.0f * dot;
                    if (d2 < 1.0f) {
                        d2 = fmaxf(d2, 0.0f);
                        float m = 1.0f - sqrtf(d2);
                        atomicAdd(&g_neg, (double)(m * m));  // unordered; x2 in finalize
                    }
                }
            }
        }
    }
}

// ---------------- finalize: sum 100 class slots + 2*neg, /N^2 ---------------
__global__ void k_out(float* __restrict__ out) {
    __shared__ double red[128];
    int tid = threadIdx.x;
    double acc = (tid < NC) ? g_pos[tid] : 0.0;
    red[tid] = acc;
    __syncthreads();
    for (int s = 64; s > 0; s >>= 1) {
        if (tid < s) red[tid] += red[tid + s];
        __syncthreads();
    }
    if (tid == 0) {
        double total = red[0] + 2.0 * g_neg;
        out[0] = (float)(total / ((double)NPTS * (double)NPTS));
    }
}

extern "C" void kernel_launch(void* const* d_in, const int* in_sizes, int n_in,
                              void* d_out, int out_size) {
    const float* z   = (const float*)d_in[0];
    const int*   lab = (const int*)d_in[1];
    float*       out = (float*)d_out;

    k_sq<<<NPTS / 256, 256>>>(z);
    k_class<<<NC, 128>>>(z, lab);
    k_screen<<<dim3(NPTS / TJ, NPTS / TI), NTHR>>>(z, lab);
    k_out<<<1, 128>>>(out);
}

// round 7
// speedup vs baseline: 5.0393x; 5.0393x over previous
#include <cuda_runtime.h>

// ContrastiveLoss: z [8192,128] fp32, labels [8192] int32.
// loss = mean over all ordered pairs of: label_eq ? d2 : relu(1 - sqrt(max(d2,0)))^2
//
// pos: closed form per class: sum_{i,j in c} d2 = 2*n_c*S_c - 2*|M_c|^2  (O(N*D))
// neg: only pairs with d2 < 1 contribute. Partial squared distance over the first
//      PSCR dims is a LOWER bound on d2 -> branchless screen at O(N^2*PSCR);
//      warp-cooperative exact 128-dim recheck for rare candidates.

#define NPTS   8192
#define DIM    128
#define NC     100
#define PSCR   8
#define TJ     256
#define NTHR   512
#define IPT    2
#define TI     (NTHR * IPT)       // 1024
#define THRESH 1.25f              // screen-out if partial d2 >= THRESH (1 + fp32 slack)
#define FULLM  0xffffffffu

// ---- scratch (no allocations allowed) ----
__device__ double g_pos[NC];      // per-class analytic pos contribution (slot write)
__device__ double g_neg;          // sum over unordered unequal pairs of relu(1-dist)^2
__device__ float  g_sq[NPTS];     // per-point squared norm

// ---------------- per-point squared norms (+ zero g_neg) --------------------
__global__ void k_sq(const float* __restrict__ z) {
    int i = blockIdx.x * blockDim.x + threadIdx.x;
    if (i == 0) g_neg = 0.0;
    if (i < NPTS) {
        const float4* zr = (const float4*)(z + (size_t)i * DIM);
        float s = 0.0f;
#pragma unroll
        for (int k = 0; k < DIM / 4; k++) {
            float4 v = zr[k];
            s = fmaf(v.x, v.x, s); s = fmaf(v.y, v.y, s);
            s = fmaf(v.z, v.z, s); s = fmaf(v.w, v.w, s);
        }
        g_sq[i] = s;
    }
}

// ---------------- per-class analytic pos term (block = class) ---------------
__global__ void __launch_bounds__(128)
k_class(const float* __restrict__ z, const int* __restrict__ lab) {
    __shared__ int    list[NPTS];      // member row indices (32KB)
    __shared__ int    s_cnt;
    __shared__ double red[128];
    const int c   = blockIdx.x;
    const int tid = threadIdx.x;

    if (tid == 0) s_cnt = 0;
    __syncthreads();
    for (int i = tid; i < NPTS; i += 128)
        if (lab[i] == c) list[atomicAdd(&s_cnt, 1)] = i;
    __syncthreads();
    const int cnt = s_cnt;

    // column pass: thread owns dim `tid`; warp lanes read consecutive dims of
    // the same row -> coalesced 128B lines, L2-resident. 4-way unroll for MLP.
    float m0 = 0.0f, m1 = 0.0f, q0 = 0.0f, q1 = 0.0f;
    int k = 0;
    for (; k + 4 <= cnt; k += 4) {
        int r0 = list[k], r1 = list[k + 1], r2 = list[k + 2], r3 = list[k + 3];
        float v0 = __ldg(z + (size_t)r0 * DIM + tid);
        float v1 = __ldg(z + (size_t)r1 * DIM + tid);
        float v2 = __ldg(z + (size_t)r2 * DIM + tid);
        float v3 = __ldg(z + (size_t)r3 * DIM + tid);
        m0 += v0 + v1;          m1 += v2 + v3;
        q0 = fmaf(v0, v0, q0);  q0 = fmaf(v1, v1, q0);
        q1 = fmaf(v2, v2, q1);  q1 = fmaf(v3, v3, q1);
    }
    for (; k < cnt; k++) {
        float v = __ldg(z + (size_t)list[k] * DIM + tid);
        m0 += v;
        q0 = fmaf(v, v, q0);
    }
    float m = m0 + m1, q = q0 + q1;
    // contribution of this dim: 2*cnt*q_d - 2*m_d^2 ; summed over dims
    red[tid] = 2.0 * (double)cnt * (double)q - 2.0 * (double)m * (double)m;
    __syncthreads();
    for (int s = 64; s > 0; s >>= 1) {
        if (tid < s) red[tid] += red[tid + s];
        __syncthreads();
    }
    if (tid == 0) g_pos[c] = red[0];
}

// ---------------- screening pass over unordered pairs (j > i) ---------------
__global__ void __launch_bounds__(NTHR)
k_screen(const float* __restrict__ z, const int* __restrict__ lab) {
    __shared__ float4 sV[TJ][2];      // first 8 dims of j rows
    __shared__ float  sP[TJ];         // partial sq norm of j
    __shared__ int    sLab[TJ];

    const int I0 = blockIdx.y * TI;
    const int J0 = blockIdx.x * TJ;
    if (J0 + TJ <= I0 + 1) return;               // no pair with j > i in block
    const bool needCheck = (J0 < I0 + TI);       // diagonal overlap

    const int tid   = threadIdx.x;
    const int lane  = tid & 31;
    const int wbase = tid & ~31;

    // stage j tile
    for (int j = tid; j < TJ; j += NTHR) {
        int jg = J0 + j;
        const float4* zr = (const float4*)(z + (size_t)jg * DIM);
        float4 v0 = zr[0], v1 = zr[1];
        float s = v0.x*v0.x + v0.y*v0.y + v0.z*v0.z + v0.w*v0.w
                + v1.x*v1.x + v1.y*v1.y + v1.z*v1.z + v1.w*v1.w;
        sV[j][0] = v0; sV[j][1] = v1;
        sP[j] = s;
        sLab[j] = lab[jg];
    }
    __syncthreads();

    // 2 i-rows per thread; store coords pre-scaled by -2 so the screen is pure FMA
    float r0[PSCR], r1[PSCR], ps0, ps1;
    int   labi0, labi1;
    {
        int ig0 = I0 + tid, ig1 = ig0 + NTHR;
        const float4* za = (const float4*)(z + (size_t)ig0 * DIM);
        const float4* zb = (const float4*)(z + (size_t)ig1 * DIM);
        float4 a0 = za[0], a1 = za[1], b0 = zb[0], b1 = zb[1];
        ps0 = a0.x*a0.x + a0.y*a0.y + a0.z*a0.z + a0.w*a0.w
            + a1.x*a1.x + a1.y*a1.y + a1.z*a1.z + a1.w*a1.w;
        ps1 = b0.x*b0.x + b0.y*b0.y + b0.z*b0.z + b0.w*b0.w
            + b1.x*b1.x + b1.y*b1.y + b1.z*b1.z + b1.w*b1.w;
        r0[0] = -2.0f*a0.x; r0[1] = -2.0f*a0.y; r0[2] = -2.0f*a0.z; r0[3] = -2.0f*a0.w;
        r0[4] = -2.0f*a1.x; r0[5] = -2.0f*a1.y; r0[6] = -2.0f*a1.z; r0[7] = -2.0f*a1.w;
        r1[0] = -2.0f*b0.x; r1[1] = -2.0f*b0.y; r1[2] = -2.0f*b0.z; r1[3] = -2.0f*b0.w;
        r1[4] = -2.0f*b1.x; r1[5] = -2.0f*b1.y; r1[6] = -2.0f*b1.z; r1[7] = -2.0f*b1.w;
        labi0 = lab[ig0]; labi1 = lab[ig1];
    }

    double wNeg = 0.0;   // per-warp accumulator (lane 0 only writes)

    for (int j = 0; j < TJ; j++) {
        float4 b0 = sV[j][0], b1 = sV[j][1];       // warp-uniform broadcast
        float  pj = sP[j];

        // pd2 = psq_i + psq_j + dot(-2*zi, zj)  (lower bound on full d2)
        float d0 = ps0 + pj;
        d0 = fmaf(r0[0], b0.x, d0); d0 = fmaf(r0[1], b0.y, d0);
        d0 = fmaf(r0[2], b0.z, d0); d0 = fmaf(r0[3], b0.w, d0);
        d0 = fmaf(r0[4], b1.x, d0); d0 = fmaf(r0[5], b1.y, d0);
        d0 = fmaf(r0[6], b1.z, d0); d0 = fmaf(r0[7], b1.w, d0);

        float d1 = ps1 + pj;
        d1 = fmaf(r1[0], b0.x, d1); d1 = fmaf(r1[1], b0.y, d1);
        d1 = fmaf(r1[2], b0.z, d1); d1 = fmaf(r1[3], b0.w, d1);
        d1 = fmaf(r1[4], b1.x, d1); d1 = fmaf(r1[5], b1.y, d1);
        d1 = fmaf(r1[6], b1.z, d1); d1 = fmaf(r1[7], b1.w, d1);

        // one warp-uniform branch per j (no per-lane divergence on the hot path)
        unsigned ball = __ballot_sync(FULLM, fminf(d0, d1) < THRESH);
        if (ball) {
            const int   jg  = J0 + j;
            const int   lj  = sLab[j];
            const float sqj = g_sq[jg];
            const float4* zjr = (const float4*)(z + (size_t)jg * DIM);
            float4 bq = zjr[lane];                 // lane's quarter of row j
            while (ball) {
                int l = __ffs(ball) - 1; ball &= ball - 1;
                float dd0 = __shfl_sync(FULLM, d0, l);
                float dd1 = __shfl_sync(FULLM, d1, l);
                int   li0 = __shfl_sync(FULLM, labi0, l);
                int   li1 = __shfl_sync(FULLM, labi1, l);
                int   ib  = I0 + wbase + l;
#pragma unroll
                for (int t = 0; t < IPT; t++) {
                    float ddt = t ? dd1 : dd0;
                    int   li  = t ? li1 : li0;
                    int   ig  = ib + t * NTHR;
                    // warp-uniform condition: all lanes agree
                    if (ddt < THRESH && (!needCheck || jg > ig) && li != lj) {
                        const float4* zir = (const float4*)(z + (size_t)ig * DIM);
                        float4 aq = zir[lane];
                        float part = aq.x*bq.x + aq.y*bq.y + aq.z*bq.z + aq.w*bq.w;
#pragma unroll
                        for (int o = 16; o; o >>= 1)
                            part += __shfl_xor_sync(FULLM, part, o);
                        if (lane == 0) {
                            // exact d2, same formula as the reference
                            float dq = g_sq[ig] + sqj - 2.0f * part;
                            if (dq < 1.0f) {
                                dq = fmaxf(dq, 0.0f);
                                float mm = 1.0f - sqrtf(dq);
                                wNeg += (double)(mm * mm);   // unordered; x2 later
                            }
                        }
                    }
                }
            }
        }
    }

    if (lane == 0 && wNeg != 0.0) atomicAdd(&g_neg, wNeg);
}

// ---------------- finalize: sum 100 class slots + 2*neg, /N^2 ---------------
__global__ void k_out(float* __restrict__ out) {
    __shared__ double red[128];
    int tid = threadIdx.x;
    red[tid] = (tid < NC) ? g_pos[tid] : 0.0;
    __syncthreads();
    for (int s = 64; s > 0; s >>= 1) {
        if (tid < s) red[tid] += red[tid + s];
        __syncthreads();
    }
    if (tid == 0) {
        double total = red[0] + 2.0 * g_neg;
        out[0] = (float)(total / ((double)NPTS * (double)NPTS));
    }
}

extern "C" void kernel_launch(void* const* d_in, const int* in_sizes, int n_in,
                              void* d_out, int out_size) {
    const float* z   = (const float*)d_in[0];
    const int*   lab = (const int*)d_in[1];
    float*       out = (float*)d_out;

    k_sq<<<NPTS / 256, 256>>>(z);
    k_class<<<NC, 128>>>(z, lab);
    k_screen<<<dim3(NPTS / TJ, NPTS / TI), NTHR>>>(z, lab);
    k_out<<<1, 128>>>(out);
}

// round 8
// speedup vs baseline: 7.0253x; 1.3941x over previous
#include <cuda_runtime.h>

// ContrastiveLoss: z [8192,128] fp32, labels [8192] int32.
// loss = mean over all ordered pairs of: label_eq ? d2 : relu(1 - sqrt(max(d2,0)))^2
//
// pos: closed form per class: sum_{i,j in c} d2 = 2*n_c*S_c - 2*|M_c|^2  (O(N*D))
// neg: only pairs with d2 < 1 contribute. Partial squared distance over the first
//      PSCR dims is a LOWER bound on d2 -> screen all N^2/2 pairs at PSCR dims;
//      warp-cooperative exact 128-dim recheck for rare candidates.
// 2 kernels total: k_class (pos + scratch init), k_screen (neg + finalize in last block).

#define NPTS   8192
#define DIM    128
#define NC     100
#define PSCR   8
#define TJ     128
#define NTHR   256
#define IPT    4
#define TI     (NTHR * IPT)       // 1024
#define GRIDX  (NPTS / TJ)        // 64
#define GRIDY  (NPTS / TI)        // 8
#define NBLK   (GRIDX * GRIDY)    // 512
#define THRESH 1.0625f            // screen-out if partial d2 >= THRESH (1 + fp32 slack)
#define FULLM  0xffffffffu

// ---- scratch (no allocations allowed) ----
__device__ double g_pos[NC];      // per-class analytic pos contribution (slot write)
__device__ double g_neg;          // sum over unordered unequal pairs of relu(1-dist)^2
__device__ int    g_ticket;       // completion counter for in-kernel finalize

// ---------------- per-class analytic pos term (block = class) ---------------
__global__ void __launch_bounds__(128)
k_class(const float* __restrict__ z, const int* __restrict__ lab) {
    __shared__ int    list[NPTS];      // member row indices (32KB)
    __shared__ int    s_cnt;
    __shared__ double red[128];
    const int c   = blockIdx.x;
    const int tid = threadIdx.x;

    if (c == 0 && tid == 0) { g_neg = 0.0; g_ticket = 0; }   // runs before k_screen

    if (tid == 0) s_cnt = 0;
    __syncthreads();
    for (int i = tid; i < NPTS; i += 128)
        if (lab[i] == c) list[atomicAdd(&s_cnt, 1)] = i;
    __syncthreads();
    const int cnt = s_cnt;

    // column pass: thread owns dim `tid`; warp lanes read consecutive dims of
    // the same row -> coalesced 128B lines, L2-resident. 4-way unroll for MLP.
    float m0 = 0.0f, m1 = 0.0f, q0 = 0.0f, q1 = 0.0f;
    int k = 0;
    for (; k + 4 <= cnt; k += 4) {
        int r0 = list[k], r1 = list[k + 1], r2 = list[k + 2], r3 = list[k + 3];
        float v0 = __ldg(z + (size_t)r0 * DIM + tid);
        float v1 = __ldg(z + (size_t)r1 * DIM + tid);
        float v2 = __ldg(z + (size_t)r2 * DIM + tid);
        float v3 = __ldg(z + (size_t)r3 * DIM + tid);
        m0 += v0 + v1;          m1 += v2 + v3;
        q0 = fmaf(v0, v0, q0);  q0 = fmaf(v1, v1, q0);
        q1 = fmaf(v2, v2, q1);  q1 = fmaf(v3, v3, q1);
    }
    for (; k < cnt; k++) {
        float v = __ldg(z + (size_t)list[k] * DIM + tid);
        m0 += v;
        q0 = fmaf(v, v, q0);
    }
    float m = m0 + m1, q = q0 + q1;
    red[tid] = 2.0 * (double)cnt * (double)q - 2.0 * (double)m * (double)m;
    __syncthreads();
    for (int s = 64; s > 0; s >>= 1) {
        if (tid < s) red[tid] += red[tid + s];
        __syncthreads();
    }
    if (tid == 0) g_pos[c] = red[0];
}

// ---------------- screen + finalize -----------------------------------------
__global__ void __launch_bounds__(NTHR)
k_screen(const float* __restrict__ z, const int* __restrict__ lab,
         float* __restrict__ out) {
    __shared__ float4 sV[TJ][2];      // first 8 dims of j rows
    __shared__ float  sT[TJ];         // THRESH - partial sq norm of j
    __shared__ int    sLab[TJ];
    __shared__ double redd[NTHR];
    __shared__ int    s_isLast;

    const int I0 = blockIdx.y * TI;
    const int J0 = blockIdx.x * TJ;
    const int tid   = threadIdx.x;
    const int lane  = tid & 31;
    const int wbase = tid & ~31;
    const bool productive = (J0 + TJ > I0 + 1);
    const bool needCheck  = (J0 < I0 + TI);

    if (productive) {
        // stage j tile
        for (int j = tid; j < TJ; j += NTHR) {
            int jg = J0 + j;
            const float4* zr = (const float4*)(z + (size_t)jg * DIM);
            float4 v0 = zr[0], v1 = zr[1];
            float s = v0.x*v0.x + v0.y*v0.y + v0.z*v0.z + v0.w*v0.w
                    + v1.x*v1.x + v1.y*v1.y + v1.z*v1.z + v1.w*v1.w;
            sV[j][0] = v0; sV[j][1] = v1;
            sT[j] = THRESH - s;
            sLab[j] = lab[jg];
        }
        __syncthreads();

        // 4 i-rows per thread, coords pre-scaled by -2 -> pure FMA screen
        float r[IPT][PSCR], ps[IPT];
        int   labi[IPT];
#pragma unroll
        for (int t = 0; t < IPT; t++) {
            int ig = I0 + tid + t * NTHR;
            const float4* za = (const float4*)(z + (size_t)ig * DIM);
            float4 a0 = za[0], a1 = za[1];
            ps[t] = a0.x*a0.x + a0.y*a0.y + a0.z*a0.z + a0.w*a0.w
                  + a1.x*a1.x + a1.y*a1.y + a1.z*a1.z + a1.w*a1.w;
            r[t][0] = -2.0f*a0.x; r[t][1] = -2.0f*a0.y;
            r[t][2] = -2.0f*a0.z; r[t][3] = -2.0f*a0.w;
            r[t][4] = -2.0f*a1.x; r[t][5] = -2.0f*a1.y;
            r[t][6] = -2.0f*a1.z; r[t][7] = -2.0f*a1.w;
            labi[t] = lab[ig];
        }

        double wNeg = 0.0;   // per-warp accumulator (lane 0 writes)

        for (int j = 0; j < TJ; j++) {
            float4 b0 = sV[j][0], b1 = sV[j][1];   // warp-uniform broadcast
            float  tj = sT[j];

            // d_t = ps_i + dot(-2*z_i, z_j); pair passes iff d_t < tj (= THRESH - ps_j)
            float d[IPT];
#pragma unroll
            for (int t = 0; t < IPT; t++) {
                float a = ps[t];
                a = fmaf(r[t][0], b0.x, a); a = fmaf(r[t][1], b0.y, a);
                a = fmaf(r[t][2], b0.z, a); a = fmaf(r[t][3], b0.w, a);
                a = fmaf(r[t][4], b1.x, a); a = fmaf(r[t][5], b1.y, a);
                a = fmaf(r[t][6], b1.z, a); a = fmaf(r[t][7], b1.w, a);
                d[t] = a;
            }
            float mn = fminf(fminf(d[0], d[1]), fminf(d[2], d[3]));

            unsigned ball = __ballot_sync(FULLM, mn < tj);
            if (ball) {
                const int jg = J0 + j;
                const int lj = sLab[j];
                const float4* zjr = (const float4*)(z + (size_t)jg * DIM);
                float4 bq = zjr[lane];                 // lane's quarter of row j
                float sqj = bq.x*bq.x + bq.y*bq.y + bq.z*bq.z + bq.w*bq.w;
#pragma unroll
                for (int o = 16; o; o >>= 1)
                    sqj += __shfl_xor_sync(FULLM, sqj, o);
                while (ball) {
                    int l = __ffs(ball) - 1; ball &= ball - 1;
                    float dd[IPT]; int li[IPT];
#pragma unroll
                    for (int t = 0; t < IPT; t++) {
                        dd[t] = __shfl_sync(FULLM, d[t], l);
                        li[t] = __shfl_sync(FULLM, labi[t], l);
                    }
                    float tjl = tj;
                    int ib = I0 + wbase + l;
#pragma unroll
                    for (int t = 0; t < IPT; t++) {
                        int ig = ib + t * NTHR;
                        // warp-uniform condition: all operands uniform
                        if (dd[t] < tjl && (!needCheck || jg > ig) && li[t] != lj) {
                            const float4* zir = (const float4*)(z + (size_t)ig * DIM);
                            float4 aq = zir[lane];
                            float part = aq.x*bq.x + aq.y*bq.y + aq.z*bq.z + aq.w*bq.w;
                            float sqi  = aq.x*aq.x + aq.y*aq.y + aq.z*aq.z + aq.w*aq.w;
#pragma unroll
                            for (int o = 16; o; o >>= 1) {
                                part += __shfl_xor_sync(FULLM, part, o);
                                sqi  += __shfl_xor_sync(FULLM, sqi, o);
                            }
                            if (lane == 0) {
                                // exact d2, same formula as the reference
                                float dq = sqi + sqj - 2.0f * part;
                                if (dq < 1.0f) {
                                    dq = fmaxf(dq, 0.0f);
                                    float mm = 1.0f - sqrtf(dq);
                                    wNeg += (double)(mm * mm);   // unordered; x2 below
                                }
                            }
                        }
                    }
                }
            }
        }
        if (lane == 0 && wNeg != 0.0) atomicAdd(&g_neg, wNeg);
    }

    // ---------------- completion ticket + in-kernel finalize ----------------
    __threadfence();
    __syncthreads();
    if (tid == 0) {
        int old = atomicAdd(&g_ticket, 1);
        s_isLast = (old == NBLK - 1);
    }
    __syncthreads();
    if (s_isLast) {
        __threadfence();
        double acc = (tid < NC) ? g_pos[tid] : 0.0;
        redd[tid] = acc;
        __syncthreads();
        for (int s = NTHR / 2; s > 0; s >>= 1) {
            if (tid < s) redd[tid] += redd[tid + s];
            __syncthreads();
        }
        if (tid == 0) {
            double neg = atomicAdd(&g_neg, 0.0);     // atomic read (L2-coherent)
            double total = redd[0] + 2.0 * neg;
            out[0] = (float)(total / ((double)NPTS * (double)NPTS));
        }
    }
}

extern "C" void kernel_launch(void* const* d_in, const int* in_sizes, int n_in,
                              void* d_out, int out_size) {
    const float* z   = (const float*)d_in[0];
    const int*   lab = (const int*)d_in[1];
    float*       out = (float*)d_out;

    k_class<<<NC, 128>>>(z, lab);
    k_screen<<<dim3(GRIDX, GRIDY), NTHR>>>(z, lab, out);
}

// round 11
// speedup vs baseline: 8.4794x; 1.2070x over previous
#include <cuda_runtime.h>

// ContrastiveLoss: z [8192,128] fp32, labels [8192] int32.
// loss = mean over all ordered pairs of: label_eq ? d2 : relu(1 - sqrt(max(d2,0)))^2
//
// pos: closed form per class: sum_{i,j in c} d2 = 2*n_c*S_c - 2*|M_c|^2  (O(N*D))
// neg: only pairs with d2 < 1 contribute. Partial squared distance over the first
//      PSCR dims is a LOWER bound on d2 -> screen all N^2/2 pairs at PSCR dims
//      (ballot batched over 4 j); warp-cooperative exact recheck for rare hits.
// 2 kernels: k_class (pos + g_sq + scratch init), k_screen (neg + finalize).

#define NPTS   8192
#define DIM    128
#define NC     100
#define PSCR   8
#define TJ     128
#define NTHR   256
#define IPT    4
#define JB     4                  // j-batch per ballot
#define TI     (NTHR * IPT)       // 1024
#define NBX    (NPTS / TJ)        // 64
#define NBY    (NPTS / TI)        // 8
#define NBLK   288                // productive blocks: sum_y (64 - 8y)
#define THRESH 1.0625f            // screen-out if partial d2 >= THRESH (1 + fp32 slack)
#define FULLM  0xffffffffu

// ---- scratch (no allocations allowed) ----
__device__ double g_pos[NC];      // per-class analytic pos contribution (slot write)
__device__ float  g_sq[NPTS];     // per-point squared norm
__device__ double g_neg;          // sum over unordered unequal pairs of relu(1-dist)^2
__device__ int    g_ticket;      // completion counter for in-kernel finalize

// ---------------- per-class pos term + per-row norms (block = class) --------
__global__ void __launch_bounds__(128)
k_class(const float* __restrict__ z, const int* __restrict__ lab) {
    __shared__ int    list[NPTS];      // member row indices (32KB)
    __shared__ int    s_cnt;
    __shared__ double red[128];
    const int c    = blockIdx.x;
    const int tid  = threadIdx.x;
    const int wid  = tid >> 5;
    const int lane = tid & 31;

    if (c == 0 && tid == 0) { g_neg = 0.0; g_ticket = 0; }   // before k_screen

    // per-row squared norms for rows r == c (mod NC); warp-cooperative
    for (int r = c + NC * wid; r < NPTS; r += NC * 4) {
        const float4* zr = (const float4*)(z + (size_t)r * DIM);
        float4 v = zr[lane];                     // 32 lanes x 4 dims = 128
        float s = v.x*v.x + v.y*v.y + v.z*v.z + v.w*v.w;
#pragma unroll
        for (int o = 16; o; o >>= 1) s += __shfl_xor_sync(FULLM, s, o);
        if (lane == 0) g_sq[r] = s;
    }

    if (tid == 0) s_cnt = 0;
    __syncthreads();
    for (int i = tid; i < NPTS; i += 128)
        if (lab[i] == c) list[atomicAdd(&s_cnt, 1)] = i;
    __syncthreads();
    const int cnt = s_cnt;

    // column pass: thread owns dim tid; lanes read consecutive dims of the
    // same row -> coalesced 128B lines, L2-resident. 4-way unroll for MLP.
    float m0 = 0.0f, m1 = 0.0f, q0 = 0.0f, q1 = 0.0f;
    int k = 0;
    for (; k + 4 <= cnt; k += 4) {
        int r0 = list[k], r1 = list[k + 1], r2 = list[k + 2], r3 = list[k + 3];
        float v0 = __ldg(z + (size_t)r0 * DIM + tid);
        float v1 = __ldg(z + (size_t)r1 * DIM + tid);
        float v2 = __ldg(z + (size_t)r2 * DIM + tid);
        float v3 = __ldg(z + (size_t)r3 * DIM + tid);
        m0 += v0 + v1;          m1 += v2 + v3;
        q0 = fmaf(v0, v0, q0);  q0 = fmaf(v1, v1, q0);
        q1 = fmaf(v2, v2, q1);  q1 = fmaf(v3, v3, q1);
    }
    for (; k < cnt; k++) {
        float v = __ldg(z + (size_t)list[k] * DIM + tid);
        m0 += v;
        q0 = fmaf(v, v, q0);
    }
    float m = m0 + m1, q = q0 + q1;
    red[tid] = 2.0 * (double)cnt * (double)q - 2.0 * (double)m * (double)m;
    __syncthreads();
    for (int s = 64; s > 0; s >>= 1) {
        if (tid < s) red[tid] += red[tid + s];
        __syncthreads();
    }
    if (tid == 0) g_pos[c] = red[0];
}

// ---------------- screen + finalize -----------------------------------------
__global__ void __launch_bounds__(NTHR, 3)
k_screen(const float* __restrict__ z, const int* __restrict__ lab,
         float* __restrict__ out) {
    __shared__ float4 sV[TJ][2];      // first 8 dims of j rows
    __shared__ float  sT[TJ];         // partial sq norm of j - THRESH
    __shared__ double redd[NTHR];
    __shared__ int    s_isLast;

    // 1D triangular grid -> (x, y): productive blocks have x >= 8y
    int bid = blockIdx.x;
    int by = 0;
    {
        int rem = bid;
#pragma unroll
        for (int y = 0; y < NBY; y++) {
            int row = NBX - 8 * y;
            if (rem >= row) { rem -= row; } else { by = y; break; }
        }
        bid = rem;
    }
    const int I0 = by * TI;
    const int J0 = (8 * by + bid) * TJ;
    const bool needCheck = (J0 < I0 + TI);       // diagonal band

    const int tid   = threadIdx.x;
    const int lane  = tid & 31;
    const int wbase = tid & ~31;

    // stage j tile
    for (int j = tid; j < TJ; j += NTHR) {
        int jg = J0 + j;
        const float4* zr = (const float4*)(z + (size_t)jg * DIM);
        float4 v0 = zr[0], v1 = zr[1];
        float s = v0.x*v0.x + v0.y*v0.y + v0.z*v0.z + v0.w*v0.w
                + v1.x*v1.x + v1.y*v1.y + v1.z*v1.z + v1.w*v1.w;
        sV[j][0] = v0; sV[j][1] = v1;
        sT[j] = s - THRESH;
    }
    __syncthreads();

    // 4 i-rows per thread, coords pre-scaled by -2 -> pure FMA screen
    float r[IPT][PSCR], ps[IPT];
#pragma unroll
    for (int t = 0; t < IPT; t++) {
        int ig = I0 + tid + t * NTHR;
        const float4* za = (const float4*)(z + (size_t)ig * DIM);
        float4 a0 = za[0], a1 = za[1];
        ps[t] = a0.x*a0.x + a0.y*a0.y + a0.z*a0.z + a0.w*a0.w
              + a1.x*a1.x + a1.y*a1.y + a1.z*a1.z + a1.w*a1.w;
        r[t][0] = -2.0f*a0.x; r[t][1] = -2.0f*a0.y;
        r[t][2] = -2.0f*a0.z; r[t][3] = -2.0f*a0.w;
        r[t][4] = -2.0f*a1.x; r[t][5] = -2.0f*a1.y;
        r[t][6] = -2.0f*a1.z; r[t][7] = -2.0f*a1.w;
    }

    double wNeg = 0.0;   // per-warp accumulator (lane 0 writes)

    for (int jb = 0; jb < TJ; jb += JB) {
        float d[JB][IPT];
        float dm[JB];
#pragma unroll
        for (int u = 0; u < JB; u++) {
            float4 b0 = sV[jb + u][0], b1 = sV[jb + u][1];   // broadcast LDS
            float  stj = sT[jb + u];
#pragma unroll
            for (int t = 0; t < IPT; t++) {
                float a = ps[t];
                a = fmaf(r[t][0], b0.x, a); a = fmaf(r[t][1], b0.y, a);
                a = fmaf(r[t][2], b0.z, a); a = fmaf(r[t][3], b0.w, a);
                a = fmaf(r[t][4], b1.x, a); a = fmaf(r[t][5], b1.y, a);
                a = fmaf(r[t][6], b1.z, a); a = fmaf(r[t][7], b1.w, a);
                d[u][t] = a;     // = ps_i - 2*dot (partial)
            }
            float mn = fminf(fminf(d[u][0], d[u][1]), fminf(d[u][2], d[u][3]));
            dm[u] = mn + stj;    // < 0  <=>  partial d2 < THRESH
        }
        float bmn = fminf(fminf(dm[0], dm[1]), fminf(dm[2], dm[3]));

        // one ballot + one (rare) branch per JB j's
        if (__ballot_sync(FULLM, bmn < 0.0f)) {
#pragma unroll
            for (int u = 0; u < JB; u++) {
                unsigned bu = __ballot_sync(FULLM, dm[u] < 0.0f);
                if (bu) {
                    const int   jg  = J0 + jb + u;
                    const int   lj  = lab[jg];
                    const float stj = sT[jb + u];
                    const float sqj = g_sq[jg];
                    const float4* zjr = (const float4*)(z + (size_t)jg * DIM);
                    float4 bq = zjr[lane];           // lane's quarter of row j
                    while (bu) {
                        int l = __ffs(bu) - 1; bu &= bu - 1;
                        float dd[IPT];
#pragma unroll
                        for (int t = 0; t < IPT; t++)
                            dd[t] = __shfl_sync(FULLM, d[u][t], l);
                        int ib = I0 + wbase + l;
#pragma unroll
                        for (int t = 0; t < IPT; t++) {
                            int ig = ib + t * NTHR;
                            // warp-uniform condition (all operands uniform)
                            if (dd[t] + stj < 0.0f &&
                                (!needCheck || jg > ig) && lab[ig] != lj) {
                                const float4* zir = (const float4*)(z + (size_t)ig * DIM);
                                float4 aq = zir[lane];
                                float part = aq.x*bq.x + aq.y*bq.y
                                           + aq.z*bq.z + aq.w*bq.w;
#pragma unroll
                                for (int o = 16; o; o >>= 1)
                                    part += __shfl_xor_sync(FULLM, part, o);
                                if (lane == 0) {
                                    // exact d2, same formula as the reference
                                    float dq = g_sq[ig] + sqj - 2.0f * part;
                                    if (dq < 1.0f) {
                                        dq = fmaxf(dq, 0.0f);
                                        float mm = 1.0f - sqrtf(dq);
                                        wNeg += (double)(mm * mm);  // x2 below
                                    }
                                }
                            }
                        }
                    }
                }
            }
        }
    }
    if (lane == 0 && wNeg != 0.0) atomicAdd(&g_neg, wNeg);

    // ---------------- completion ticket + in-kernel finalize ----------------
    __threadfence();
    __syncthreads();
    if (tid == 0) {
        int old = atomicAdd(&g_ticket, 1);
        s_isLast = (old == NBLK - 1);
    }
    __syncthreads();
    if (s_isLast) {
        __threadfence();
        redd[tid] = (tid < NC) ? g_pos[tid] : 0.0;
        __syncthreads();
        for (int s = NTHR / 2; s > 0; s >>= 1) {
            if (tid < s) redd[tid] += redd[tid + s];
            __syncthreads();
        }
        if (tid == 0) {
            double neg = atomicAdd(&g_neg, 0.0);     // atomic read
            double total = redd[0] + 2.0 * neg;
            out[0] = (float)(total / ((double)NPTS * (double)NPTS));
        }
    }
}

extern "C" void kernel_launch(void* const* d_in, const int* in_sizes, int n_in,
                              void* d_out, int out_size) {
    const float* z   = (const float*)d_in[0];
    const int*   lab = (const int*)d_in[1];
    float*       out = (float*)d_out;

    k_class<<<NC, 128>>>(z, lab);
    k_screen<<<NBLK, NTHR>>>(z, lab, out);
}

// round 13
// speedup vs baseline: 8.7692x; 1.0342x over previous
#include <cuda_runtime.h>

// ContrastiveLoss: z [8192,128] fp32, labels [8192] int32.
// loss = mean over all ordered pairs of: label_eq ? d2 : relu(1 - sqrt(max(d2,0)))^2
//
// pos: closed form per class: sum_{i,j in c} d2 = 2*n_c*S_c - 2*|M_c|^2  (O(N*D))
// neg: only pairs with d2 < 1 contribute. Partial squared distance over the first
//      PSCR dims is a LOWER bound on d2 -> screen all N^2/2 pairs at 8 dims
//      (ballot batched over 4 j); warp-cooperative exact recheck for rare hits.
// SINGLE fused kernel: blocks 0..99 = class pos, blocks 100..675 = screen,
// last block (ticket) finalizes and resets cross-replay state.

#define NPTS   8192
#define DIM    128
#define NC     100
#define TJ     64
#define NTHR   256
#define IPT    4
#define JB     4                  // j-batch per ballot
#define TI     (NTHR * IPT)       // 1024
#define NBY    (NPTS / TI)        // 8
#define NJX    (NPTS / TJ)        // 128
#define NSCR   576                // productive screen blocks: sum_y (128 - 16y)
#define NBLK   (NSCR + NC)        // 676
#define THRESH 1.0625f            // screen-out if partial d2 >= THRESH (1 + fp32 slack)
#define FULLM  0xffffffffu

// ---- scratch (no allocations allowed) ----
__device__ double g_pos[NC];       // per-class analytic pos contribution (slot write)
__device__ double g_neg    = 0.0;  // unordered unequal-pair sum; reset by finalizer
__device__ int    g_ticket = 0;    // completion counter; reset by finalizer

__global__ void __launch_bounds__(NTHR, 3)
k_fused(const float* __restrict__ z, const int* __restrict__ lab,
        float* __restrict__ out) {
    __shared__ int    list[NPTS];          // class blocks: member rows (32KB)
    __shared__ float  sM[NTHR], sQ[NTHR];  // class blocks: per-(dim,half) partials
    __shared__ float4 sV[TJ][2];           // screen: first 8 dims of j rows
    __shared__ float  sT[TJ];              // screen: partial sq norm of j - THRESH
    __shared__ double redd[NTHR];
    __shared__ int    s_cnt, s_isLast;

    const int tid   = threadIdx.x;
    const int lane  = tid & 31;
    const int wbase = tid & ~31;

    if ((int)blockIdx.x < NC) {
        // ================= class block: analytic pos term ====================
        const int c = blockIdx.x;
        if (tid == 0) s_cnt = 0;
        __syncthreads();
        for (int i = tid; i < NPTS; i += NTHR)
            if (lab[i] == c) list[atomicAdd(&s_cnt, 1)] = i;
        __syncthreads();
        const int cnt = s_cnt;

        // thread owns (dim = tid&127, half = tid>>7); lanes read consecutive
        // dims of the same row -> coalesced 128B lines, L2-resident.
        const int d = tid & 127, half = tid >> 7;
        float m = 0.0f, q = 0.0f;
        for (int k = half; k < cnt; k += 2) {
            float v = __ldg(z + (size_t)list[k] * DIM + d);
            m += v;
            q = fmaf(v, v, q);
        }
        sM[tid] = m; sQ[tid] = q;
        __syncthreads();
        if (tid < 128) {
            float mm = sM[tid] + sM[tid + 128];
            float qq = sQ[tid] + sQ[tid + 128];
            // contribution of this dim: 2*cnt*q_d - 2*m_d^2
            redd[tid] = 2.0 * (double)cnt * (double)qq - 2.0 * (double)mm * (double)mm;
        } else {
            redd[tid] = 0.0;
        }
        __syncthreads();
        for (int s = 128; s > 0; s >>= 1) {
            if (tid < s) redd[tid] += redd[tid + s];
            __syncthreads();
        }
        if (tid == 0) g_pos[c] = redd[0];
    } else {
        // ================= screen block ======================================
        // 1D triangular decode: row by has (128 - 16*by) blocks
        int rem = (int)blockIdx.x - NC;
        int by = 0;
#pragma unroll
        for (int y = 0; y < NBY; y++) {
            int row = NJX - 16 * y;
            if (rem >= row) { rem -= row; } else { by = y; break; }
        }
        const int I0 = by * TI;
        const int J0 = (16 * by + rem) * TJ;
        const bool needCheck = (J0 < I0 + TI);   // diagonal band

        // stage j tile
        for (int j = tid; j < TJ; j += NTHR) {
            int jg = J0 + j;
            const float4* zr = (const float4*)(z + (size_t)jg * DIM);
            float4 v0 = zr[0], v1 = zr[1];
            float s = v0.x*v0.x + v0.y*v0.y + v0.z*v0.z + v0.w*v0.w
                    + v1.x*v1.x + v1.y*v1.y + v1.z*v1.z + v1.w*v1.w;
            sV[j][0] = v0; sV[j][1] = v1;
            sT[j] = s - THRESH;
        }
        __syncthreads();

        // 4 i-rows per thread, coords pre-scaled by -2 -> pure FMA screen
        float r[IPT][8], ps[IPT];
#pragma unroll
        for (int t = 0; t < IPT; t++) {
            int ig = I0 + tid + t * NTHR;
            const float4* za = (const float4*)(z + (size_t)ig * DIM);
            float4 a0 = za[0], a1 = za[1];
            ps[t] = a0.x*a0.x + a0.y*a0.y + a0.z*a0.z + a0.w*a0.w
                  + a1.x*a1.x + a1.y*a1.y + a1.z*a1.z + a1.w*a1.w;
            r[t][0] = -2.0f*a0.x; r[t][1] = -2.0f*a0.y;
            r[t][2] = -2.0f*a0.z; r[t][3] = -2.0f*a0.w;
            r[t][4] = -2.0f*a1.x; r[t][5] = -2.0f*a1.y;
            r[t][6] = -2.0f*a1.z; r[t][7] = -2.0f*a1.w;
        }

        double wNeg = 0.0;   // per-warp accumulator (lane 0 writes)

        for (int jb = 0; jb < TJ; jb += JB) {
            float d[JB][IPT];
            float dm[JB];
#pragma unroll
            for (int u = 0; u < JB; u++) {
                float4 b0 = sV[jb + u][0], b1 = sV[jb + u][1];   // LDS broadcast
                float  stj = sT[jb + u];
#pragma unroll
                for (int t = 0; t < IPT; t++) {
                    float a = ps[t];
                    a = fmaf(r[t][0], b0.x, a); a = fmaf(r[t][1], b0.y, a);
                    a = fmaf(r[t][2], b0.z, a); a = fmaf(r[t][3], b0.w, a);
                    a = fmaf(r[t][4], b1.x, a); a = fmaf(r[t][5], b1.y, a);
                    a = fmaf(r[t][6], b1.z, a); a = fmaf(r[t][7], b1.w, a);
                    d[u][t] = a;     // = ps_i - 2*dot (partial)
                }
                float mn = fminf(fminf(d[u][0], d[u][1]), fminf(d[u][2], d[u][3]));
                dm[u] = mn + stj;    // < 0  <=>  partial d2 < THRESH
            }
            float bmn = fminf(fminf(dm[0], dm[1]), fminf(dm[2], dm[3]));

            // one ballot + one (rare) branch per JB j's
            if (__ballot_sync(FULLM, bmn < 0.0f)) {
#pragma unroll
                for (int u = 0; u < JB; u++) {
                    unsigned bu = __ballot_sync(FULLM, dm[u] < 0.0f);
                    if (bu) {
                        const int   jg  = J0 + jb + u;
                        const int   lj  = lab[jg];
                        const float stj = sT[jb + u];
                        const float4* zjr = (const float4*)(z + (size_t)jg * DIM);
                        float4 bq = zjr[lane];           // lane's quarter of row j
                        float sqj = bq.x*bq.x + bq.y*bq.y + bq.z*bq.z + bq.w*bq.w;
#pragma unroll
                        for (int o = 16; o; o >>= 1)
                            sqj += __shfl_xor_sync(FULLM, sqj, o);
                        while (bu) {
                            int l = __ffs(bu) - 1; bu &= bu - 1;
                            float dd[IPT];
#pragma unroll
                            for (int t = 0; t < IPT; t++)
                                dd[t] = __shfl_sync(FULLM, d[u][t], l);
                            int ib = I0 + wbase + l;
#pragma unroll
                            for (int t = 0; t < IPT; t++) {
                                int ig = ib + t * NTHR;
                                // warp-uniform condition (all operands uniform)
                                if (dd[t] + stj < 0.0f &&
                                    (!needCheck || jg > ig) && lab[ig] != lj) {
                                    const float4* zir =
                                        (const float4*)(z + (size_t)ig * DIM);
                                    float4 aq = zir[lane];
                                    float part = aq.x*bq.x + aq.y*bq.y
                                               + aq.z*bq.z + aq.w*bq.w;
                                    float sqi  = aq.x*aq.x + aq.y*aq.y
                                               + aq.z*aq.z + aq.w*aq.w;
#pragma unroll
                                    for (int o = 16; o; o >>= 1) {
                                        part += __shfl_xor_sync(FULLM, part, o);
                                        sqi  += __shfl_xor_sync(FULLM, sqi, o);
                                    }
                                    if (lane == 0) {
                                        // exact d2, same formula as the reference
                                        float dq = sqi + sqj - 2.0f * part;
                                        if (dq < 1.0f) {
                                            dq = fmaxf(dq, 0.0f);
                                            float mm = 1.0f - sqrtf(dq);
                                            wNeg += (double)(mm * mm); // x2 below
                                        }
                                    }
                                }
                            }
                        }
                    }
                }
            }
        }
        if (lane == 0 && wNeg != 0.0) atomicAdd(&g_neg, wNeg);
    }

    // ================= completion ticket + finalize ==========================
    __threadfence();
    __syncthreads();
    if (tid == 0) {
        int old = atomicAdd(&g_ticket, 1);
        s_isLast = (old == NBLK - 1);
    }
    __syncthreads();
    if (s_isLast) {
        __threadfence();
        redd[tid] = (tid < NC) ? g_pos[tid] : 0.0;
        __syncthreads();
        for (int s = 128; s > 0; s >>= 1) {
            if (tid < s) redd[tid] += redd[tid + s];
            __syncthreads();
        }
        if (tid == 0) {
            double neg = atomicAdd(&g_neg, 0.0);     // atomic read
            double total = redd[0] + 2.0 * neg;
            out[0] = (float)(total / ((double)NPTS * (double)NPTS));
            g_neg = 0.0;       // reset cross-replay state for next graph replay
            g_ticket = 0;
        }
    }
}

extern "C" void kernel_launch(void* const* d_in, const int* in_sizes, int n_in,
                              void* d_out, int out_size) {
    const float* z   = (const float*)d_in[0];
    const int*   lab = (const int*)d_in[1];
    float*       out = (float*)d_out;

    k_fused<<<NBLK, NTHR>>>(z, lab, out);
}